// round 2
// baseline (speedup 1.0000x reference)
#include <cuda_runtime.h>

// Problem constants (from reference)
#define NB   64      // batch
#define NT   60      // targets per batch
#define NK   3       // anchors in this scale
#define S0   80
#define S1   80
#define BODY 85

// ground_true elements: 64*3*80*80*85 = 104,448,000
// no_obj_mask elements: 64*3*80*80    =   1,228,800
#define GT_ELEMS   104448000LL
#define MASK_ELEMS 1228800LL

#define NV_WORDS   ((NB * NT) / 4)   // 960 uint32 words covering 3840 bytes

// anchors / STRIDE (=8)
__constant__ float c_aw[9] = {10.f/8.f, 16.f/8.f, 33.f/8.f, 30.f/8.f, 62.f/8.f,
                              59.f/8.f, 116.f/8.f, 156.f/8.f, 373.f/8.f};
__constant__ float c_ah[9] = {13.f/8.f, 30.f/8.f, 23.f/8.f, 61.f/8.f, 45.f/8.f,
                              119.f/8.f, 90.f/8.f, 198.f/8.f, 326.f/8.f};

// 0 = uint8 (1 byte/bool), 1 = int32 (4 bytes/bool), 2 = float32
__device__ int g_valid_mode;

// ---------------------------------------------------------------------------
// Kernel 0: sniff the on-wire layout of the `valid` (jax bool) buffer.
// int32 layout  -> every 32-bit word is 0 or 1
// float32 layout-> every 32-bit word is 0 or 0x3f800000
// uint8 layout  -> random 0/1 bytes -> words outside both sets
// Deterministic for fixed input.
// ---------------------------------------------------------------------------
__global__ void sniff_valid_kernel(const unsigned int* __restrict__ v) {
    __shared__ int not01, notf;
    if (threadIdx.x == 0) { not01 = 0; notf = 0; }
    __syncthreads();
    for (int i = threadIdx.x; i < NV_WORDS; i += blockDim.x) {
        unsigned int w = v[i];
        if (w > 1u)                        atomicOr(&not01, 1);
        if (w != 0u && w != 0x3f800000u)   atomicOr(&notf, 1);
    }
    __syncthreads();
    if (threadIdx.x == 0) {
        int mode;
        if (!not01)      mode = 1;   // int32 bools
        else if (!notf)  mode = 2;   // float32 bools
        else             mode = 0;   // packed uint8 bools
        g_valid_mode = mode;
    }
}

// ---------------------------------------------------------------------------
// Kernel 1: bulk fill. ground_true region -> 0.0f, mask region -> 1.0f.
// GT_ELEMS divisible by 4, so each float4 is uniform. Pure write roofline.
// ---------------------------------------------------------------------------
__global__ void fill_kernel(float4* __restrict__ out, long long n4, long long gt4) {
    long long idx = (long long)blockIdx.x * blockDim.x + threadIdx.x;
    if (idx < n4) {
        float v = (idx < gt4) ? 0.0f : 1.0f;
        out[idx] = make_float4(v, v, v, v);
    }
}

// ---------------------------------------------------------------------------
// Kernel 2: target assignment scatter.
// One block per batch. Threads compute per-target IoU argmax in parallel;
// thread 0 applies writes serially in ascending t (last duplicate wins,
// matching in-order scatter semantics).
// ---------------------------------------------------------------------------
__global__ void scatter_kernel(const float* __restrict__ txywh,   // [B,T,4]
                               const int*   __restrict__ tcls,    // [B,T]
                               const void*  __restrict__ validp,  // [B,T] bool (layout per g_valid_mode)
                               float* __restrict__ gt,            // [B,K,S0,S1,85]
                               float* __restrict__ mask)          // [B,K,S0,S1]
{
    const int b = blockIdx.x;
    const int t = threadIdx.x;

    __shared__ int   s_base[NT];
    __shared__ float s_x[NT], s_y[NT], s_w[NT], s_h[NT];
    __shared__ int   s_cls[NT];

    if (t < NT) {
        const int idx = b * NT + t;
        const float* p = txywh + (long long)idx * 4;
        float x = p[0] * (float)S0;
        float y = p[1] * (float)S1;
        float w = p[2] * (float)S0;
        float h = p[3] * (float)S1;

        // argmax IoU over 9 anchors, first-max-wins (strict >)
        float best_iou = -1.0f;
        int   best = 0;
        float wh = w * h;
        #pragma unroll
        for (int a = 0; a < 9; a++) {
            float inter = fminf(w, c_aw[a]) * fminf(h, c_ah[a]);
            inter = fmaxf(inter, 0.0f);
            float uni = wh + c_aw[a] * c_ah[a] - inter;
            float iou = inter / uni;
            if (iou > best_iou) { best_iou = iou; best = a; }
        }

        // read `valid` per sniffed layout
        int mode = g_valid_mode;
        bool vld;
        if (mode == 1)      vld = ((const int*)validp)[idx] != 0;
        else if (mode == 2) vld = ((const float*)validp)[idx] != 0.0f;
        else                vld = ((const unsigned char*)validp)[idx] != 0;

        // ANCHOR_MASK = {0,1,2}; k = best % 3 == best when in-scale
        bool in_scale = (best < NK) && vld;
        int base = -1;
        if (in_scale) {
            int i = (int)floorf(x);   // x in [0,80) -> i in [0,79]
            int j = (int)floorf(y);
            base = ((b * NK + best) * S0 + j) * S1 + i;
        }
        s_base[t] = base;
        s_x[t] = x; s_y[t] = y; s_w[t] = w; s_h[t] = h;
        s_cls[t] = tcls[idx];
    }
    __syncthreads();

    if (t == 0) {
        for (int u = 0; u < NT; u++) {
            int base = s_base[u];
            if (base >= 0) {
                float* g = gt + (long long)base * BODY;
                g[0] = s_x[u];
                g[1] = s_y[u];
                g[2] = s_w[u];
                g[3] = s_h[u];
                g[4] = 1.0f;
                g[5 + s_cls[u]] = 1.0f;
                mask[base] = 0.0f;
            }
        }
    }
}

extern "C" void kernel_launch(void* const* d_in, const int* in_sizes, int n_in,
                              void* d_out, int out_size) {
    const float* txywh = (const float*)d_in[0];
    const int*   tcls  = (const int*)d_in[1];
    const void*  valid = d_in[2];

    float* out  = (float*)d_out;
    float* gt   = out;
    float* mask = out + GT_ELEMS;

    const long long n4  = (GT_ELEMS + MASK_ELEMS) / 4;  // 26,419,200
    const long long gt4 = GT_ELEMS / 4;                 // 26,112,000

    sniff_valid_kernel<<<1, 256>>>((const unsigned int*)valid);

    int threads = 256;
    long long blocks = (n4 + threads - 1) / threads;
    fill_kernel<<<(unsigned int)blocks, threads>>>((float4*)out, n4, gt4);

    scatter_kernel<<<NB, 64>>>(txywh, tcls, valid, gt, mask);
}